// round 3
// baseline (speedup 1.0000x reference)
#include <cuda_runtime.h>
#include <cstddef>

// Problem constants
#define BB    128
#define NN    1024
#define LL    512
#define DD    64
#define TPB   256            // threads per block (main kernel), 1 token row per thread
#define RB    32             // regions per smem tile
#define NTILE (NN / TPB)     // 4 token tiles

// Scratch (no device allocations allowed -> __device__ globals)
__device__ float g_part[3 * BB * NTILE];   // partial sum(max) per (sim, b, tile)
__device__ int   g_ntok[BB];
__device__ int   g_nreg[BB];
__device__ float g_ntokf[BB];

// Packed f32x2 FMA (sm_100+): two fp32 FMAs per fma-pipe slot
#define FMA2(acc, a, b) asm("fma.rn.f32x2 %0, %1, %2, %0;" : "+l"(acc) : "l"(a), "l"(b))

__device__ __forceinline__ float2 u64_as_f2(unsigned long long v) {
    float2 r;
    r.x = __uint_as_float((unsigned int)(v & 0xffffffffull));
    r.y = __uint_as_float((unsigned int)(v >> 32));
    return r;
}

// ---------------------------------------------------------------------------
// prep: per-batch valid counts from prefix masks
// ---------------------------------------------------------------------------
__global__ void prep_kernel(const float* __restrict__ tmask,
                            const float* __restrict__ imask) {
    __shared__ float red[256];
    int b = blockIdx.x, t = threadIdx.x;

    float s = 0.f;
    for (int i = t; i < NN; i += 256) s += tmask[b * NN + i];
    red[t] = s; __syncthreads();
    for (int o = 128; o > 0; o >>= 1) { if (t < o) red[t] += red[t + o]; __syncthreads(); }
    if (t == 0) { g_ntok[b] = (int)(red[0] + 0.5f); g_ntokf[b] = red[0]; }
    __syncthreads();

    s = 0.f;
    for (int i = t; i < LL; i += 256) s += imask[b * LL + i];
    red[t] = s; __syncthreads();
    for (int o = 128; o > 0; o >>= 1) { if (t < o) red[t] += red[t + o]; __syncthreads(); }
    if (t == 0) g_nreg[b] = (int)(red[0] + 0.5f);
}

// ---------------------------------------------------------------------------
// main: fused (token x region) dot + row-max + partial token sum
// grid = (NTILE, BB, 3); sim 0 = anchor, 1 = Simp (text gathered), 2 = Iimp (image gathered)
// ---------------------------------------------------------------------------
__global__ __launch_bounds__(TPB) void main_kernel(
    const float* __restrict__ text,
    const float* __restrict__ image,
    const int* __restrict__ Iidx,
    const int* __restrict__ Sidx) {

    const int tile = blockIdx.x, b = blockIdx.y, s = blockIdx.z;
    const int tb = (s == 1) ? Sidx[b] : b;   // text batch index
    const int ib = (s == 2) ? Iidx[b] : b;   // image batch index
    const int ntok = g_ntok[tb];
    const int nreg = g_nreg[ib];
    const int slot = (s * BB + b) * NTILE + tile;
    const int t = threadIdx.x;

    if (tile * TPB >= ntok) {                // whole tile past valid prefix
        if (t == 0) g_part[slot] = 0.f;
        return;
    }

    __shared__ float sI[RB * DD];            // 8 KB region tile
    __shared__ float red[TPB];

    const int n = tile * TPB + t;
    const bool tv = (n < ntok);

    // Token row resident in registers as 32 packed f32x2 values
    unsigned long long tr[DD / 2];
    if (tv) {
        const ulonglong2* trow =
            reinterpret_cast<const ulonglong2*>(text + ((size_t)tb * NN + n) * DD);
        #pragma unroll
        for (int i = 0; i < DD / 4; i++) {
            ulonglong2 v = trow[i];
            tr[2 * i] = v.x; tr[2 * i + 1] = v.y;
        }
    }

    float mx = __int_as_float(0xff800000);   // -inf
    const float4* isrc =
        reinterpret_cast<const float4*>(image + (size_t)ib * LL * DD);

    for (int lb = 0; lb < nreg; lb += RB) {
        const int lcount = min(RB, nreg - lb);
        __syncthreads();
        const int n4 = lcount * (DD / 4);
        for (int i = t; i < n4; i += TPB)
            reinterpret_cast<float4*>(sI)[i] = isrc[lb * (DD / 4) + i];
        __syncthreads();

        if (tv) {
            for (int l = 0; l < lcount; l++) {
                // all threads read the same region row -> smem broadcast
                const ulonglong2* sv =
                    reinterpret_cast<const ulonglong2*>(sI + l * DD);
                unsigned long long c0 = 0ull, c1 = 0ull, c2 = 0ull, c3 = 0ull;
                #pragma unroll
                for (int j = 0; j < DD / 8; j++) {    // 8 iters: 2x LDS.128 + 4x FFMA2
                    ulonglong2 v0 = sv[2 * j], v1 = sv[2 * j + 1];
                    FMA2(c0, tr[4 * j],     v0.x);
                    FMA2(c1, tr[4 * j + 1], v0.y);
                    FMA2(c2, tr[4 * j + 2], v1.x);
                    FMA2(c3, tr[4 * j + 3], v1.y);
                }
                float2 f0 = u64_as_f2(c0), f1 = u64_as_f2(c1);
                float2 f2 = u64_as_f2(c2), f3 = u64_as_f2(c3);
                float dot = ((f0.x + f0.y) + (f1.x + f1.y)) +
                            ((f2.x + f2.y) + (f3.x + f3.y));
                mx = fmaxf(mx, dot);
            }
        }
    }

    // partial sum of per-token maxes over this tile (prefix mask -> weight 1)
    red[t] = tv ? mx : 0.f;
    __syncthreads();
    for (int o = TPB / 2; o > 0; o >>= 1) {
        if (t < o) red[t] += red[t + o];
        __syncthreads();
    }
    if (t == 0) g_part[slot] = red[0];
}

// ---------------------------------------------------------------------------
// final: sims -> hinge -> scalar loss
// ---------------------------------------------------------------------------
__global__ void final_kernel(const int* __restrict__ Iidx,
                             const int* __restrict__ Sidx,
                             float* __restrict__ out) {
    __shared__ float red[BB];
    const int b = threadIdx.x;   // 128 threads

    float anchor = 0.f, simp = 0.f, iimp = 0.f;
    #pragma unroll
    for (int tile = 0; tile < NTILE; tile++) {
        anchor += g_part[(0 * BB + b) * NTILE + tile];
        simp   += g_part[(1 * BB + b) * NTILE + tile];
        iimp   += g_part[(2 * BB + b) * NTILE + tile];
    }
    anchor /= g_ntokf[b];
    simp   /= g_ntokf[Sidx[b]];
    iimp   /= g_ntokf[b];

    float per = fmaxf(1.f + iimp - anchor, 0.f) + fmaxf(1.f + simp - anchor, 0.f);
    red[b] = per;
    __syncthreads();
    for (int o = BB / 2; o > 0; o >>= 1) {
        if (b < o) red[b] += red[b + o];
        __syncthreads();
    }
    if (b == 0) out[0] = red[0] / (float)BB;
}

// ---------------------------------------------------------------------------
extern "C" void kernel_launch(void* const* d_in, const int* in_sizes, int n_in,
                              void* d_out, int out_size) {
    const float* text  = (const float*)d_in[0];   // (B, N, D) f32
    const float* image = (const float*)d_in[1];   // (B, L, D) f32
    const float* tmask = (const float*)d_in[2];   // (B, N) f32
    const float* imask = (const float*)d_in[3];   // (B, L) f32
    const int*   Iidx  = (const int*)d_in[4];     // (B,) i32
    const int*   Sidx  = (const int*)d_in[5];     // (B,) i32
    (void)in_sizes; (void)n_in; (void)out_size;

    prep_kernel<<<BB, 256>>>(tmask, imask);
    dim3 grid(NTILE, BB, 3);
    main_kernel<<<grid, TPB>>>(text, image, Iidx, Sidx);
    final_kernel<<<1, BB>>>(Iidx, Sidx, (float*)d_out);
}

// round 5
// speedup vs baseline: 1.0393x; 1.0393x over previous
#include <cuda_runtime.h>
#include <cstddef>

// Problem constants
#define BB    128
#define NN    1024
#define LL    512
#define DD    64
#define TPB   256            // threads per block (main kernel), 1 token row per thread
#define RB    64             // regions per smem tile (16 KB per stage)
#define NTILE (NN / TPB)     // 4 token tiles

// Scratch (no device allocations allowed -> __device__ globals)
__device__ float g_part[3 * BB * NTILE];   // partial sum(max) per (sim, b, tile)
__device__ int   g_ntok[BB];
__device__ int   g_nreg[BB];
__device__ float g_ntokf[BB];

// Packed f32x2 ops (sm_100+): two fp32 ops per fma/alu-pipe slot
#define FMA2(acc, a, b) asm("fma.rn.f32x2 %0, %1, %2, %0;" : "+l"(acc) : "l"(a), "l"(b))
#define ADD2(d, a, b)   asm("add.rn.f32x2 %0, %1, %2;"     : "=l"(d)  : "l"(a), "l"(b))

#define CP_ASYNC16(dst_s, src_g) \
    asm volatile("cp.async.cg.shared.global [%0], [%1], 16;" :: "r"(dst_s), "l"(src_g))
#define CP_COMMIT()  asm volatile("cp.async.commit_group;" ::: "memory")
#define CP_WAIT1()   asm volatile("cp.async.wait_group 1;" ::: "memory")

__device__ __forceinline__ float2 u64_as_f2(unsigned long long v) {
    float2 r;
    r.x = __uint_as_float((unsigned int)(v & 0xffffffffull));
    r.y = __uint_as_float((unsigned int)(v >> 32));
    return r;
}

// ---------------------------------------------------------------------------
// prep: per-batch valid counts from prefix masks
// ---------------------------------------------------------------------------
__global__ void prep_kernel(const float* __restrict__ tmask,
                            const float* __restrict__ imask) {
    __shared__ float red[256];
    int b = blockIdx.x, t = threadIdx.x;

    float s = 0.f;
    for (int i = t; i < NN; i += 256) s += tmask[b * NN + i];
    red[t] = s; __syncthreads();
    for (int o = 128; o > 0; o >>= 1) { if (t < o) red[t] += red[t + o]; __syncthreads(); }
    if (t == 0) { g_ntok[b] = (int)(red[0] + 0.5f); g_ntokf[b] = red[0]; }
    __syncthreads();

    s = 0.f;
    for (int i = t; i < LL; i += 256) s += imask[b * LL + i];
    red[t] = s; __syncthreads();
    for (int o = 128; o > 0; o >>= 1) { if (t < o) red[t] += red[t + o]; __syncthreads(); }
    if (t == 0) g_nreg[b] = (int)(red[0] + 0.5f);
}

// ---------------------------------------------------------------------------
// main: fused (token x region) dot + row-max + partial token sum
// grid = (NTILE, BB, 3); sim 0 = anchor, 1 = Simp (text gathered), 2 = Iimp (image gathered)
// Double-buffered cp.async region tiles overlap GMEM->SMEM with compute.
// ---------------------------------------------------------------------------
__global__ __launch_bounds__(TPB) void main_kernel(
    const float* __restrict__ text,
    const float* __restrict__ image,
    const int* __restrict__ Iidx,
    const int* __restrict__ Sidx) {

    const int tile = blockIdx.x, b = blockIdx.y, s = blockIdx.z;
    const int tb = (s == 1) ? Sidx[b] : b;   // text batch index
    const int ib = (s == 2) ? Iidx[b] : b;   // image batch index
    const int ntok = g_ntok[tb];
    const int nreg = g_nreg[ib];
    const int slot = (s * BB + b) * NTILE + tile;
    const int t = threadIdx.x;

    if (tile * TPB >= ntok) {                // whole tile past valid prefix
        if (t == 0) g_part[slot] = 0.f;
        return;
    }

    __shared__ float sI[2][RB * DD];         // 2 x 16 KB region tiles
    __shared__ float red[TPB];

    const float4* isrc =
        reinterpret_cast<const float4*>(image + (size_t)ib * LL * DD);
    const int nchunk = (nreg + RB - 1) / RB;

    // Prefetch chunk 0 into stage 0 (full RB rows is safe: LL % RB == 0).
    {
        const float4* src = isrc;            // chunk 0
        #pragma unroll
        for (int i = 0; i < (RB * DD / 4) / TPB; i++) {
            int idx = i * TPB + t;
            unsigned int ds = (unsigned int)__cvta_generic_to_shared(
                reinterpret_cast<float4*>(sI[0]) + idx);
            CP_ASYNC16(ds, src + idx);
        }
        CP_COMMIT();
    }

    const int n = tile * TPB + t;
    const bool tv = (n < ntok);

    // Token row resident in registers as 32 packed f32x2 values
    unsigned long long tr[DD / 2];
    if (tv) {
        const ulonglong2* trow =
            reinterpret_cast<const ulonglong2*>(text + ((size_t)tb * NN + n) * DD);
        #pragma unroll
        for (int i = 0; i < DD / 4; i++) {
            ulonglong2 v = trow[i];
            tr[2 * i] = v.x; tr[2 * i + 1] = v.y;
        }
    }

    float mx = __int_as_float(0xff800000);   // -inf

    for (int c = 0; c < nchunk; c++) {
        // Prefetch next chunk into the other stage.
        if (c + 1 < nchunk) {
            const float4* src = isrc + (c + 1) * RB * (DD / 4);
            float4* dstp = reinterpret_cast<float4*>(sI[(c + 1) & 1]);
            #pragma unroll
            for (int i = 0; i < (RB * DD / 4) / TPB; i++) {
                int idx = i * TPB + t;
                unsigned int ds = (unsigned int)__cvta_generic_to_shared(dstp + idx);
                CP_ASYNC16(ds, src + idx);
            }
        }
        CP_COMMIT();
        CP_WAIT1();                          // chunk c's group complete
        __syncthreads();

        const int lcount = min(RB, nreg - c * RB);
        const float* stage = sI[c & 1];

        if (tv) {
            for (int l = 0; l < lcount; l++) {
                // all threads read the same region row -> smem broadcast
                const ulonglong2* sv =
                    reinterpret_cast<const ulonglong2*>(stage + l * DD);
                unsigned long long c0 = 0ull, c1 = 0ull, c2 = 0ull, c3 = 0ull;
                #pragma unroll
                for (int j = 0; j < DD / 8; j++) {    // 8 iters: 2x LDS.128 + 4x FFMA2
                    ulonglong2 v0 = sv[2 * j], v1 = sv[2 * j + 1];
                    FMA2(c0, tr[4 * j],     v0.x);
                    FMA2(c1, tr[4 * j + 1], v0.y);
                    FMA2(c2, tr[4 * j + 2], v1.x);
                    FMA2(c3, tr[4 * j + 3], v1.y);
                }
                // packed tree-add epilogue: 3 packed adds + 1 fadd + 1 fmax
                unsigned long long s01, s23, sall;
                ADD2(s01, c0, c1);
                ADD2(s23, c2, c3);
                ADD2(sall, s01, s23);
                float2 f = u64_as_f2(sall);
                mx = fmaxf(mx, f.x + f.y);
            }
        }
        __syncthreads();                     // stage (c&1) free before c+1's prefetch reuses it
    }

    // partial sum of per-token maxes over this tile (prefix mask -> weight 1)
    red[t] = tv ? mx : 0.f;
    __syncthreads();
    for (int o = TPB / 2; o > 0; o >>= 1) {
        if (t < o) red[t] += red[t + o];
        __syncthreads();
    }
    if (t == 0) g_part[slot] = red[0];
}

// ---------------------------------------------------------------------------
// final: sims -> hinge -> scalar loss
// ---------------------------------------------------------------------------
__global__ void final_kernel(const int* __restrict__ Iidx,
                             const int* __restrict__ Sidx,
                             float* __restrict__ out) {
    __shared__ float red[BB];
    const int b = threadIdx.x;   // 128 threads

    float anchor = 0.f, simp = 0.f, iimp = 0.f;
    #pragma unroll
    for (int tile = 0; tile < NTILE; tile++) {
        anchor += g_part[(0 * BB + b) * NTILE + tile];
        simp   += g_part[(1 * BB + b) * NTILE + tile];
        iimp   += g_part[(2 * BB + b) * NTILE + tile];
    }
    anchor /= g_ntokf[b];
    simp   /= g_ntokf[Sidx[b]];
    iimp   /= g_ntokf[b];

    float per = fmaxf(1.f + iimp - anchor, 0.f) + fmaxf(1.f + simp - anchor, 0.f);
    red[b] = per;
    __syncthreads();
    for (int o = BB / 2; o > 0; o >>= 1) {
        if (b < o) red[b] += red[b + o];
        __syncthreads();
    }
    if (b == 0) out[0] = red[0] / (float)BB;
}

// ---------------------------------------------------------------------------
extern "C" void kernel_launch(void* const* d_in, const int* in_sizes, int n_in,
                              void* d_out, int out_size) {
    const float* text  = (const float*)d_in[0];   // (B, N, D) f32
    const float* image = (const float*)d_in[1];   // (B, L, D) f32
    const float* tmask = (const float*)d_in[2];   // (B, N) f32
    const float* imask = (const float*)d_in[3];   // (B, L) f32
    const int*   Iidx  = (const int*)d_in[4];     // (B,) i32
    const int*   Sidx  = (const int*)d_in[5];     // (B,) i32
    (void)in_sizes; (void)n_in; (void)out_size;

    prep_kernel<<<BB, 256>>>(tmask, imask);
    dim3 grid(NTILE, BB, 3);
    main_kernel<<<grid, TPB>>>(text, image, Iidx, Sidx);
    final_kernel<<<1, BB>>>(Iidx, Sidx, (float*)d_out);
}